// round 5
// baseline (speedup 1.0000x reference)
#include <cuda_runtime.h>

#define BLK   192      // threads: 2 quads x 24 nodes x 4 colgroups
#define IPB   8        // batch items per block (2 quads x 4 items)
#define NNODE 24
#define HSTR  68       // smem row stride: 68 % 32 == 4 -> conflict-free float4 LDS

typedef unsigned long long u64;

__device__ __forceinline__ u64 pack2(float lo, float hi) {
    u64 d; asm("mov.b64 %0, {%1,%2};" : "=l"(d) : "f"(lo), "f"(hi)); return d;
}
__device__ __forceinline__ void unpack2(u64 v, float& lo, float& hi) {
    asm("mov.b64 {%0,%1}, %2;" : "=f"(lo), "=f"(hi) : "l"(v));
}
__device__ __forceinline__ u64 fma2(u64 a, u64 b, u64 c) {
    u64 d; asm("fma.rn.f32x2 %0, %1, %2, %3;" : "=l"(d) : "l"(a), "l"(b), "l"(c)); return d;
}

// One GCN layer, register-blocked: thread computes 4 rows (same node, 4 items)
// x 2*PAIRS output columns. g = A*h fused (self + <=2 parents), out = relu(g@W+b).
// Weight loads amortized over the 4 rows -> 4x less weight traffic on crossbar.
template<int FIN, int WSTR, int PAIRS, int KU>
__device__ __forceinline__ void gcn_layer_rb(
    float* __restrict__ hbuf,
    const float* __restrict__ Ws,   // [FIN][WSTR] smem
    const float* __restrict__ bs,   // [WSTR] smem
    int coloff,                     // 2*PAIRS*colgroup
    int r0, int rp0, int rp1,       // rows for item j=0 (self, parent0, parent1)
    float ns, float wA, float wB)
{
    constexpr int RSTR = NNODE * HSTR;    // +1 item
    u64 acc[4][PAIRS];
    {
        const u64* bv = (const u64*)(bs + coloff);
        #pragma unroll
        for (int j = 0; j < 4; ++j)
            #pragma unroll
            for (int p = 0; p < PAIRS; ++p) acc[j][p] = bv[p];
    }
    const float* s0 = hbuf + r0  * HSTR;
    const float* s1 = hbuf + rp0 * HSTR;
    const float* s2 = hbuf + rp1 * HSTR;
    const float* Wc = Ws + coloff;

    constexpr int KT4 = FIN & ~3;
    #pragma unroll KU
    for (int kt = 0; kt < KT4; kt += 4) {
        u64 G[4][4];
        #pragma unroll
        for (int j = 0; j < 4; ++j) {
            float4 a = *(const float4*)(s0 + j * RSTR + kt);
            float4 b = *(const float4*)(s1 + j * RSTR + kt);
            float4 c = *(const float4*)(s2 + j * RSTR + kt);
            float g0 = fmaf(ns, a.x, fmaf(wA, b.x, wB * c.x));
            float g1 = fmaf(ns, a.y, fmaf(wA, b.y, wB * c.y));
            float g2 = fmaf(ns, a.z, fmaf(wA, b.z, wB * c.z));
            float g3 = fmaf(ns, a.w, fmaf(wA, b.w, wB * c.w));
            G[j][0] = pack2(g0, g0); G[j][1] = pack2(g1, g1);
            G[j][2] = pack2(g2, g2); G[j][3] = pack2(g3, g3);
        }
        #pragma unroll
        for (int kk = 0; kk < 4; ++kk) {
            u64 w[PAIRS];
            const u64* wv = (const u64*)(Wc + (kt + kk) * WSTR);
            #pragma unroll
            for (int p = 0; p < PAIRS; ++p) w[p] = wv[p];
            #pragma unroll
            for (int j = 0; j < 4; ++j)
                #pragma unroll
                for (int p = 0; p < PAIRS; ++p)
                    acc[j][p] = fma2(G[j][kk], w[p], acc[j][p]);
        }
    }
    if (FIN & 2) {   // tail k-pair (layer 1: k = 8,9)
        constexpr int kt = KT4;
        u64 G[4][2];
        #pragma unroll
        for (int j = 0; j < 4; ++j) {
            float2 a = *(const float2*)(s0 + j * RSTR + kt);
            float2 b = *(const float2*)(s1 + j * RSTR + kt);
            float2 c = *(const float2*)(s2 + j * RSTR + kt);
            float g0 = fmaf(ns, a.x, fmaf(wA, b.x, wB * c.x));
            float g1 = fmaf(ns, a.y, fmaf(wA, b.y, wB * c.y));
            G[j][0] = pack2(g0, g0); G[j][1] = pack2(g1, g1);
        }
        #pragma unroll
        for (int kk = 0; kk < 2; ++kk) {
            u64 w[PAIRS];
            const u64* wv = (const u64*)(Wc + (kt + kk) * WSTR);
            #pragma unroll
            for (int p = 0; p < PAIRS; ++p) w[p] = wv[p];
            #pragma unroll
            for (int j = 0; j < 4; ++j)
                #pragma unroll
                for (int p = 0; p < PAIRS; ++p)
                    acc[j][p] = fma2(G[j][kk], w[p], acc[j][p]);
        }
    }

    __syncthreads();   // everyone done READING hbuf
    float* d0 = hbuf + r0 * HSTR + coloff;
    #pragma unroll
    for (int j = 0; j < 4; ++j)
        #pragma unroll
        for (int q = 0; q < PAIRS / 2; ++q) {
            float x0, x1, x2, x3;
            unpack2(acc[j][2*q],   x0, x1);
            unpack2(acc[j][2*q+1], x2, x3);
            float4 v;
            v.x = fmaxf(x0, 0.0f); v.y = fmaxf(x1, 0.0f);
            v.z = fmaxf(x2, 0.0f); v.w = fmaxf(x3, 0.0f);
            *(float4*)(d0 + j * RSTR + 4*q) = v;
        }
    __syncthreads();   // writes visible before next layer reads
}

// smem floats: W1s 640 | b1s 64 | W3s 4096 | b3s 64 | W2s 1024(64x16) | b2s 16 |
//              deg/ns/wA/wB/p0/p1/pc 24 each | f64 1 | pad 3 | hbuf 192*68
#define HBUF_OFF    6076
#define SMEM_FLOATS (HBUF_OFF + BLK * HSTR)
#define SMEM_BYTES  (SMEM_FLOATS * 4)

__global__ void __launch_bounds__(BLK, 2)
gnn_gcn_fused_kernel(
    const float* __restrict__ x,
    const float* __restrict__ W1, const float* __restrict__ b1,
    const float* __restrict__ W3, const float* __restrict__ b3,
    const float* __restrict__ W2, const float* __restrict__ b2,
    const int* __restrict__ eiw,    // edge_index raw 32-bit words (int32 OR int64 data)
    int nE, int B,
    float* __restrict__ out)
{
    extern __shared__ float sm[];
    float* W1s  = sm;                // 640  (10 x 64)
    float* b1s  = sm + 640;          // 64
    float* W3s  = sm + 704;          // 4096 (64 x 64)
    float* b3s  = sm + 4800;         // 64
    float* W2s  = sm + 4864;         // 1024 (64 x 16, cols 10-15 zero)
    float* b2s  = sm + 5888;         // 16
    float* degS = sm + 5904;         // 24
    float* nsS  = sm + 5928;         // 24
    float* wAS  = sm + 5952;         // 24
    float* wBS  = sm + 5976;         // 24
    int*   p0S  = (int*)(sm + 6000); // 24
    int*   p1S  = (int*)(sm + 6024); // 24
    int*   pcS  = (int*)(sm + 6048); // 24
    int*   f64S = (int*)(sm + 6072); // 1
    float* hbuf = sm + HBUF_OFF;     // 192 x 68, 16B aligned

    const int tid = threadIdx.x;

    // ---- stage weights ----
    for (int i = tid; i < 640;  i += BLK) W1s[i] = W1[i];
    for (int i = tid; i < 64;   i += BLK) b1s[i] = b1[i];
    for (int i = tid; i < 4096; i += BLK) W3s[i] = W3[i];
    for (int i = tid; i < 64;   i += BLK) b3s[i] = b3[i];
    for (int i = tid; i < 1024; i += BLK) {          // W2 padded 10 -> 16 cols
        int row = i >> 4, c = i & 15;
        W2s[i] = (c < 10) ? W2[row * 10 + c] : 0.0f;
    }
    if (tid < 16) b2s[tid] = (tid < 10) ? b2[tid] : 0.0f;

    // ---- dtype sniff, IN-BOUNDS ONLY: int64 LE small values -> odd words zero;
    //      int32 -> odd words contain odd-indexed src entries (nonzero). ----
    if (tid == 0) {
        int odd_nonzero = 0;
        #pragma unroll
        for (int e = 1; e < 32; e += 2) odd_nonzero |= eiw[e];
        f64S[0] = (odd_nonzero == 0) ? 1 : 0;
    }

    // ---- build GCN norm from edge_index (deg counted at dst + self loop) ----
    if (tid < NNODE) { degS[tid] = 1.0f; pcS[tid] = 0; }
    __syncthreads();
    const int is64 = f64S[0];
    if (tid < nE) {
        int d = is64 ? eiw[2 * (nE + tid)] : eiw[nE + tid];
        atomicAdd(&degS[d & 31], 1.0f);
    }
    __syncthreads();
    if (tid < nE) {
        int s = (is64 ? eiw[2 * tid]        : eiw[tid])      & 31;
        int d = (is64 ? eiw[2 * (nE + tid)] : eiw[nE + tid]) & 31;
        int slot = atomicAdd(&pcS[d], 1);
        if      (slot == 0) p0S[d] = s;
        else if (slot == 1) p1S[d] = s;
    }
    __syncthreads();
    if (tid < NNODE) {
        float di = rsqrtf(degS[tid]);
        nsS[tid] = di * di;                       // self-loop weight
        int c = pcS[tid];
        int pa = 0, pb = 0; float wa = 0.0f, wb = 0.0f;
        if (c > 0) { pa = p0S[tid]; wa = rsqrtf(degS[pa]) * di; }
        if (c > 1) { pb = p1S[tid]; wb = rsqrtf(degS[pb]) * di; }
        p0S[tid] = pa; p1S[tid] = pb; wAS[tid] = wa; wBS[tid] = wb;
    }

    // ---- stage X (coalesced gmem -> strided smem rows) ----
    const long base = (long)blockIdx.x * (IPB * NNODE * 10);
    long remain = (long)B * NNODE * 10 - base;
    int lim = remain < (IPB * NNODE * 10) ? (int)remain : (IPB * NNODE * 10);
    for (int i = tid; i < lim; i += BLK) {
        int rr = i / 10, j = i - rr * 10;
        hbuf[rr * HSTR + j] = x[base + i];
    }
    __syncthreads();

    // ---- per-thread identity: quad q (4 items), node n, colgroup c ----
    const int q   = tid / 96;            // 0..1
    const int rem = tid - 96 * q;
    const int n   = rem >> 2;            // 0..23
    const int c   = rem & 3;             // 0..3
    const float ns = nsS[n], wa = wAS[n], wb = wBS[n];
    const int ib  = q * 4;               // first local item of this thread
    const int r0  = ib * NNODE + n;
    const int rq0 = ib * NNODE + p0S[n];
    const int rq1 = ib * NNODE + p1S[n];

    // ---- three fused GCN layers (in-place in hbuf) ----
    gcn_layer_rb<10, 64, 8, 2>(hbuf, W1s, b1s, c * 16, r0, rq0, rq1, ns, wa, wb);
    gcn_layer_rb<64, 64, 8, 2>(hbuf, W3s, b3s, c * 16, r0, rq0, rq1, ns, wa, wb);
    gcn_layer_rb<64, 16, 2, 4>(hbuf, W2s, b2s, c * 4,  r0, rq0, rq1, ns, wa, wb);

    // ---- mean pool over 24 nodes, write [IPB,10] per block ----
    if (tid < IPB * 10) {
        int i = tid / 10, j = tid - 10 * i;
        long gitem = (long)blockIdx.x * IPB + i;
        if (gitem < B) {
            float s = 0.0f;
            #pragma unroll
            for (int m = 0; m < NNODE; ++m)
                s += hbuf[(i * NNODE + m) * HSTR + j];
            out[gitem * 10 + j] = s * (1.0f / 24.0f);
        }
    }
}

extern "C" void kernel_launch(void* const* d_in, const int* in_sizes, int n_in,
                              void* d_out, int out_size)
{
    const float* x  = (const float*)d_in[0];
    const float* W1 = (const float*)d_in[1];
    const float* b1 = (const float*)d_in[2];
    const float* W3 = (const float*)d_in[3];
    const float* b3 = (const float*)d_in[4];
    const float* W2 = (const float*)d_in[5];
    const float* b2 = (const float*)d_in[6];
    const int*   ei = (const int*)d_in[7];   // raw words; dtype sniffed in-kernel

    const int B  = in_sizes[0] / (NNODE * 10);
    const int nE = in_sizes[7] / 2;
    const int grid = (B + IPB - 1) / IPB;

    cudaFuncSetAttribute(gnn_gcn_fused_kernel,
                         cudaFuncAttributeMaxDynamicSharedMemorySize, SMEM_BYTES);
    gnn_gcn_fused_kernel<<<grid, BLK, SMEM_BYTES>>>(
        x, W1, b1, W3, b3, W2, b2, ei, nE, B, (float*)d_out);
}